// round 1
// baseline (speedup 1.0000x reference)
#include <cuda_runtime.h>
#include <math.h>

#define Bv   2
#define Sv   2048
#define Dv   1024
#define Hv   16
#define DKv  64
#define DFFv 4096
#define Mv   (Bv * Sv)   // 4096 rows

// ---------------- scratch (device globals; no allocation allowed) ----------
__device__ float g_q[Mv * Dv];
__device__ float g_k[Mv * Dv];
__device__ float g_v[Mv * Dv];
__device__ float g_attn[Mv * Dv];
__device__ float g_x1[Mv * Dv];
__device__ float g_h[Mv * DFFv];
__device__ float g_y[Mv * Dv];

// ---------------- generic tiled fp32 GEMM: C = A[MxK] @ W[KxN] (+bias)(+res)(+relu)
template <bool BIAS, bool RELU, bool RES>
__global__ void __launch_bounds__(256) gemm_k(
    const float* __restrict__ A, const float* __restrict__ W,
    const float* __restrict__ bias, const float* __restrict__ res,
    float* __restrict__ C, int M, int N, int K)
{
    __shared__ float Ast[16][128];   // transposed A tile: Ast[k][m]
    __shared__ float Bst[16][128];   // Bst[k][n]

    const int tid = threadIdx.x;
    const int tx = tid & 15;         // col group (8 cols each)
    const int ty = tid >> 4;         // row group (8 rows each)
    const int rowBase = blockIdx.y * 128;
    const int colBase = blockIdx.x * 128;

    float acc[8][8];
#pragma unroll
    for (int i = 0; i < 8; i++)
#pragma unroll
        for (int j = 0; j < 8; j++) acc[i][j] = 0.f;

    for (int kt = 0; kt < K; kt += 16) {
        // A tile: 128 rows x 16 k  (512 float4, 2 per thread), store transposed
#pragma unroll
        for (int i = 0; i < 2; i++) {
            int f4 = tid + i * 256;
            int ar = f4 >> 2;                 // 0..127
            int ac = (f4 & 3) * 4;            // 0,4,8,12
            float4 v = *reinterpret_cast<const float4*>(
                &A[(size_t)(rowBase + ar) * K + kt + ac]);
            Ast[ac + 0][ar] = v.x;
            Ast[ac + 1][ar] = v.y;
            Ast[ac + 2][ar] = v.z;
            Ast[ac + 3][ar] = v.w;
        }
        // B tile: 16 k x 128 n (512 float4, 2 per thread), direct
#pragma unroll
        for (int i = 0; i < 2; i++) {
            int f4 = tid + i * 256;
            int br = f4 >> 5;                 // 0..15
            int bc = (f4 & 31) * 4;           // 0..124
            *reinterpret_cast<float4*>(&Bst[br][bc]) =
                *reinterpret_cast<const float4*>(
                    &W[(size_t)(kt + br) * N + colBase + bc]);
        }
        __syncthreads();

#pragma unroll
        for (int k = 0; k < 16; k++) {
            float a[8], b[8];
            *reinterpret_cast<float4*>(&a[0]) = *reinterpret_cast<float4*>(&Ast[k][ty * 8]);
            *reinterpret_cast<float4*>(&a[4]) = *reinterpret_cast<float4*>(&Ast[k][ty * 8 + 4]);
            *reinterpret_cast<float4*>(&b[0]) = *reinterpret_cast<float4*>(&Bst[k][tx * 8]);
            *reinterpret_cast<float4*>(&b[4]) = *reinterpret_cast<float4*>(&Bst[k][tx * 8 + 4]);
#pragma unroll
            for (int i = 0; i < 8; i++)
#pragma unroll
                for (int j = 0; j < 8; j++)
                    acc[i][j] = fmaf(a[i], b[j], acc[i][j]);
        }
        __syncthreads();
    }

    // epilogue
#pragma unroll
    for (int i = 0; i < 8; i++) {
        const int r = rowBase + ty * 8 + i;
#pragma unroll
        for (int j = 0; j < 8; j += 4) {
            const int c = colBase + tx * 8 + j;
            float4 o;
            o.x = acc[i][j + 0];
            o.y = acc[i][j + 1];
            o.z = acc[i][j + 2];
            o.w = acc[i][j + 3];
            if (BIAS) {
                float4 bb = *reinterpret_cast<const float4*>(&bias[c]);
                o.x += bb.x; o.y += bb.y; o.z += bb.z; o.w += bb.w;
            }
            if (RES) {
                float4 rr = *reinterpret_cast<const float4*>(&res[(size_t)r * N + c]);
                o.x += rr.x; o.y += rr.y; o.z += rr.z; o.w += rr.w;
            }
            if (RELU) {
                o.x = fmaxf(o.x, 0.f); o.y = fmaxf(o.y, 0.f);
                o.z = fmaxf(o.z, 0.f); o.w = fmaxf(o.w, 0.f);
            }
            *reinterpret_cast<float4*>(&C[(size_t)r * N + c]) = o;
        }
    }
}

// ---------------- flash attention (fp32, DK=64) -----------------------------
// One block per (b, h, 128-query tile). 64-key chunks, online softmax.
// Shared: Qst[64][128] | Kst[64][64] | Vs[64][64] | Pst[64][128]  = 96 KB
__global__ void __launch_bounds__(256) attn_k(
    const float* __restrict__ Q, const float* __restrict__ K,
    const float* __restrict__ V, float* __restrict__ O)
{
    extern __shared__ float sm[];
    float* Qst = sm;                  // [dk][q]    64*128
    float* Kst = Qst + 64 * 128;      // [dk][key]  64*64
    float* Vs  = Kst + 64 * 64;       // [key][dk]  64*64
    float* Pst = Vs  + 64 * 64;       // [key][q]   64*128

    const int tid = threadIdx.x;
    const int tx = tid & 15;          // 4 cols each
    const int ty = tid >> 4;          // 8 rows each
    const int qBase = blockIdx.x * 128;
    const int h = blockIdx.y;
    const int b = blockIdx.z;
    const size_t base = (size_t)b * Sv * Dv + (size_t)h * DKv;

    // load Q tile, pre-scaled by 1/sqrt(64), transposed
#pragma unroll
    for (int i = 0; i < 8; i++) {
        int f4 = tid + i * 256;       // 0..2047
        int qr = f4 >> 4;             // 0..127
        int qc = (f4 & 15) * 4;       // 0..60
        float4 v = *reinterpret_cast<const float4*>(
            &Q[base + (size_t)(qBase + qr) * Dv + qc]);
        Qst[(qc + 0) * 128 + qr] = v.x * 0.125f;
        Qst[(qc + 1) * 128 + qr] = v.y * 0.125f;
        Qst[(qc + 2) * 128 + qr] = v.z * 0.125f;
        Qst[(qc + 3) * 128 + qr] = v.w * 0.125f;
    }

    float m[8], l[8], o[8][4];
#pragma unroll
    for (int i = 0; i < 8; i++) {
        m[i] = -1e30f; l[i] = 0.f;
#pragma unroll
        for (int j = 0; j < 4; j++) o[i][j] = 0.f;
    }

    for (int kt = 0; kt < Sv; kt += 64) {
        __syncthreads();  // prev PV-GEMM done before overwriting Kst/Vs
        // load K (transposed) and V chunk (64x64, 4 float4 per thread each)
#pragma unroll
        for (int i = 0; i < 4; i++) {
            int f4 = tid + i * 256;
            int kr = f4 >> 4;              // key row 0..63
            int kc = (f4 & 15) * 4;        // dk 0..60
            float4 kv = *reinterpret_cast<const float4*>(
                &K[base + (size_t)(kt + kr) * Dv + kc]);
            Kst[(kc + 0) * 64 + kr] = kv.x;
            Kst[(kc + 1) * 64 + kr] = kv.y;
            Kst[(kc + 2) * 64 + kr] = kv.z;
            Kst[(kc + 3) * 64 + kr] = kv.w;
            float4 vv = *reinterpret_cast<const float4*>(
                &V[base + (size_t)(kt + kr) * Dv + kc]);
            *reinterpret_cast<float4*>(&Vs[kr * 64 + kc]) = vv;
        }
        __syncthreads();

        // scores S = (Q/8) @ K^T   : thread tile 8x4
        float s[8][4];
#pragma unroll
        for (int i = 0; i < 8; i++)
#pragma unroll
            for (int j = 0; j < 4; j++) s[i][j] = 0.f;
#pragma unroll
        for (int k = 0; k < 64; k++) {
            float a[8], bb[4];
            *reinterpret_cast<float4*>(&a[0]) = *reinterpret_cast<float4*>(&Qst[k * 128 + ty * 8]);
            *reinterpret_cast<float4*>(&a[4]) = *reinterpret_cast<float4*>(&Qst[k * 128 + ty * 8 + 4]);
            *reinterpret_cast<float4*>(&bb[0]) = *reinterpret_cast<float4*>(&Kst[k * 64 + tx * 4]);
#pragma unroll
            for (int i = 0; i < 8; i++)
#pragma unroll
                for (int j = 0; j < 4; j++)
                    s[i][j] = fmaf(a[i], bb[j], s[i][j]);
        }

        // online softmax (reduce across the 16 tx lanes sharing each row)
#pragma unroll
        for (int i = 0; i < 8; i++) {
            float mi = fmaxf(fmaxf(s[i][0], s[i][1]), fmaxf(s[i][2], s[i][3]));
#pragma unroll
            for (int d = 1; d < 16; d <<= 1)
                mi = fmaxf(mi, __shfl_xor_sync(0xffffffffu, mi, d));
            float mn = fmaxf(m[i], mi);
            float corr = __expf(m[i] - mn);
            m[i] = mn;
            float ls = 0.f;
#pragma unroll
            for (int j = 0; j < 4; j++) {
                s[i][j] = __expf(s[i][j] - mn);
                ls += s[i][j];
            }
#pragma unroll
            for (int d = 1; d < 16; d <<= 1)
                ls += __shfl_xor_sync(0xffffffffu, ls, d);
            l[i] = l[i] * corr + ls;
#pragma unroll
            for (int j = 0; j < 4; j++) o[i][j] *= corr;
        }

        // stage P (transposed) for the PV GEMM
#pragma unroll
        for (int i = 0; i < 8; i++)
#pragma unroll
            for (int j = 0; j < 4; j++)
                Pst[(tx * 4 + j) * 128 + ty * 8 + i] = s[i][j];
        __syncthreads();

        // O += P @ V
#pragma unroll
        for (int k = 0; k < 64; k++) {
            float a[8], bb[4];
            *reinterpret_cast<float4*>(&a[0]) = *reinterpret_cast<float4*>(&Pst[k * 128 + ty * 8]);
            *reinterpret_cast<float4*>(&a[4]) = *reinterpret_cast<float4*>(&Pst[k * 128 + ty * 8 + 4]);
            *reinterpret_cast<float4*>(&bb[0]) = *reinterpret_cast<float4*>(&Vs[k * 64 + tx * 4]);
#pragma unroll
            for (int i = 0; i < 8; i++)
#pragma unroll
                for (int j = 0; j < 4; j++)
                    o[i][j] = fmaf(a[i], bb[j], o[i][j]);
        }
    }

    // normalize and write out (layout [b,s,h*64+dk] so O-proj GEMM reads directly)
#pragma unroll
    for (int i = 0; i < 8; i++) {
        float inv = 1.f / l[i];
        float4 ov;
        ov.x = o[i][0] * inv; ov.y = o[i][1] * inv;
        ov.z = o[i][2] * inv; ov.w = o[i][3] * inv;
        *reinterpret_cast<float4*>(
            &O[base + (size_t)(qBase + ty * 8 + i) * Dv + tx * 4]) = ov;
    }
}

// ---------------- layernorm (ddof=1, scalar gamma/beta) ---------------------
__global__ void __launch_bounds__(256) ln_k(
    const float* __restrict__ X, float* __restrict__ Y,
    const float* __restrict__ gamma, const float* __restrict__ beta)
{
    __shared__ float sh[64];
    const int row = blockIdx.x;
    const int tid = threadIdx.x;
    const float4 v = *reinterpret_cast<const float4*>(X + (size_t)row * Dv + tid * 4);
    float s = v.x + v.y + v.z + v.w;
    float sq = fmaf(v.x, v.x, fmaf(v.y, v.y, fmaf(v.z, v.z, v.w * v.w)));
#pragma unroll
    for (int d = 16; d > 0; d >>= 1) {
        s  += __shfl_xor_sync(0xffffffffu, s, d);
        sq += __shfl_xor_sync(0xffffffffu, sq, d);
    }
    const int w = tid >> 5, lane = tid & 31;
    if (lane == 0) { sh[w] = s; sh[32 + w] = sq; }
    __syncthreads();
    if (tid == 0) {
        float S = 0.f, SQ = 0.f;
        for (int i = 0; i < 8; i++) { S += sh[i]; SQ += sh[32 + i]; }
        sh[48] = S; sh[49] = SQ;
    }
    __syncthreads();
    const float S = sh[48], SQ = sh[49];
    const float mean = S * (1.f / 1024.f);
    const float var = (SQ - 1024.f * mean * mean) * (1.f / 1023.f);
    const float scale = gamma[0] / sqrtf(var + 1e-5f);
    const float be = beta[0];
    float4 ov;
    ov.x = (v.x - mean) * scale + be;
    ov.y = (v.y - mean) * scale + be;
    ov.z = (v.z - mean) * scale + be;
    ov.w = (v.w - mean) * scale + be;
    *reinterpret_cast<float4*>(Y + (size_t)row * Dv + tid * 4) = ov;
}

// ---------------- launch ----------------------------------------------------
extern "C" void kernel_launch(void* const* d_in, const int* in_sizes, int n_in,
                              void* d_out, int out_size)
{
    (void)in_sizes; (void)n_in; (void)out_size;
    const float* x      = (const float*)d_in[0];
    // d_in[1] src_mask: no-op in reference
    const float* wq     = (const float*)d_in[2];
    const float* wk     = (const float*)d_in[3];
    const float* wv     = (const float*)d_in[4];
    const float* wo     = (const float*)d_in[5];
    const float* w1     = (const float*)d_in[6];
    const float* b1     = (const float*)d_in[7];
    const float* w2     = (const float*)d_in[8];
    const float* b2     = (const float*)d_in[9];
    const float* gamma1 = (const float*)d_in[10];
    const float* beta1  = (const float*)d_in[11];
    const float* gamma2 = (const float*)d_in[12];
    const float* beta2  = (const float*)d_in[13];
    float* out = (float*)d_out;

    float *q, *k, *v, *attn, *x1, *hbuf, *ybuf;
    cudaGetSymbolAddress((void**)&q,    g_q);
    cudaGetSymbolAddress((void**)&k,    g_k);
    cudaGetSymbolAddress((void**)&v,    g_v);
    cudaGetSymbolAddress((void**)&attn, g_attn);
    cudaGetSymbolAddress((void**)&x1,   g_x1);
    cudaGetSymbolAddress((void**)&hbuf, g_h);
    cudaGetSymbolAddress((void**)&ybuf, g_y);

    cudaFuncSetAttribute(attn_k, cudaFuncAttributeMaxDynamicSharedMemorySize, 96 * 1024);

    const dim3 thr(256);
    const dim3 gD(Dv / 128, Mv / 128);     // (8, 32)
    const dim3 gF(DFFv / 128, Mv / 128);   // (32, 32)

    // Q, K, V projections
    gemm_k<false, false, false><<<gD, thr>>>(x, wq, nullptr, nullptr, q, Mv, Dv, Dv);
    gemm_k<false, false, false><<<gD, thr>>>(x, wk, nullptr, nullptr, k, Mv, Dv, Dv);
    gemm_k<false, false, false><<<gD, thr>>>(x, wv, nullptr, nullptr, v, Mv, Dv, Dv);

    // attention
    attn_k<<<dim3(Sv / 128, Hv, Bv), thr, 96 * 1024>>>(q, k, v, attn);

    // O projection + residual, then LN1
    gemm_k<false, false, true><<<gD, thr>>>(attn, wo, nullptr, x, ybuf, Mv, Dv, Dv);
    ln_k<<<Mv, 256>>>(ybuf, x1, gamma1, beta1);

    // FFN
    gemm_k<true, true, false><<<gF, thr>>>(x1, w1, b1, nullptr, hbuf, Mv, DFFv, Dv);
    gemm_k<true, false, true><<<gD, thr>>>(hbuf, w2, b2, x1, ybuf, Mv, Dv, DFFv);
    ln_k<<<Mv, 256>>>(ybuf, out, gamma2, beta2);
}

// round 4
// speedup vs baseline: 1.6979x; 1.6979x over previous
#include <cuda_runtime.h>
#include <cuda_bf16.h>
#include <cstdint>
#include <math.h>

#define Bv   2
#define Sv   2048
#define Dv   1024
#define Hv   16
#define DKv  64
#define DFFv 4096
#define Mv   (Bv * Sv)   // 4096 rows

// ---------------- scratch (device globals; no allocation allowed) ----------
__device__ float g_q[Mv * Dv];
__device__ float g_k[Mv * Dv];
__device__ float g_v[Mv * Dv];
__device__ float g_x1[Mv * Dv];
__device__ float g_y[Mv * Dv];

__device__ __nv_bfloat16 g_xh[Mv * Dv],  g_xl[Mv * Dv];
__device__ __nv_bfloat16 g_ah[Mv * Dv],  g_al[Mv * Dv];
__device__ __nv_bfloat16 g_x1h[Mv * Dv], g_x1l[Mv * Dv];
__device__ __nv_bfloat16 g_hh[(size_t)Mv * DFFv], g_hl[(size_t)Mv * DFFv];

__device__ __nv_bfloat16 g_wqh[Dv * Dv], g_wql[Dv * Dv];
__device__ __nv_bfloat16 g_wkh[Dv * Dv], g_wkl[Dv * Dv];
__device__ __nv_bfloat16 g_wvh[Dv * Dv], g_wvl[Dv * Dv];
__device__ __nv_bfloat16 g_woh[Dv * Dv], g_wol[Dv * Dv];
__device__ __nv_bfloat16 g_w1h[Dv * DFFv], g_w1l[Dv * DFFv];   // transposed: [DFF, D]
__device__ __nv_bfloat16 g_w2h[Dv * DFFv], g_w2l[Dv * DFFv];   // transposed: [D, DFF]

// ---------------- PTX helpers (base sm_80+ only; no tcgen05) ----------------
static __device__ __forceinline__ uint32_t s2u(const void* p) {
    uint32_t a;
    asm("{ .reg .u64 t; cvta.to.shared.u64 t, %1; cvt.u32.u64 %0, t; }"
        : "=r"(a) : "l"(p));
    return a;
}

static __device__ __forceinline__ void ldsm4(uint32_t* r, uint32_t addr) {
    asm volatile("ldmatrix.sync.aligned.m8n8.x4.shared.b16 {%0,%1,%2,%3}, [%4];"
        : "=r"(r[0]), "=r"(r[1]), "=r"(r[2]), "=r"(r[3]) : "r"(addr));
}

static __device__ __forceinline__ void mma16816(
    float* d, const uint32_t* a, const uint32_t* b)
{
    asm volatile("mma.sync.aligned.m16n8k16.row.col.f32.bf16.bf16.f32 "
        "{%0,%1,%2,%3}, {%4,%5,%6,%7}, {%8,%9}, {%0,%1,%2,%3};"
        : "+f"(d[0]), "+f"(d[1]), "+f"(d[2]), "+f"(d[3])
        : "r"(a[0]), "r"(a[1]), "r"(a[2]), "r"(a[3]), "r"(b[0]), "r"(b[1]));
}

#define CP16(dst, src) \
    asm volatile("cp.async.cg.shared.global [%0], [%1], 16;" \
                 :: "r"(dst), "l"(src))
#define CP_COMMIT() asm volatile("cp.async.commit_group;" ::: "memory")
#define CP_WAIT0()  asm volatile("cp.async.wait_group 0;" ::: "memory")
#define CP_WAIT1()  asm volatile("cp.async.wait_group 1;" ::: "memory")

// ---------------- bf16 hi/lo split helpers ----------------------------------
static __device__ __forceinline__ void store_split4(
    __nv_bfloat16* __restrict__ hi, __nv_bfloat16* __restrict__ lo,
    size_t off, float4 v)
{
    __nv_bfloat16 h0 = __float2bfloat16(v.x), h1 = __float2bfloat16(v.y);
    __nv_bfloat16 h2 = __float2bfloat16(v.z), h3 = __float2bfloat16(v.w);
    __nv_bfloat16 l0 = __float2bfloat16(v.x - __bfloat162float(h0));
    __nv_bfloat16 l1 = __float2bfloat16(v.y - __bfloat162float(h1));
    __nv_bfloat16 l2 = __float2bfloat16(v.z - __bfloat162float(h2));
    __nv_bfloat16 l3 = __float2bfloat16(v.w - __bfloat162float(h3));
    __nv_bfloat162 ph0, ph1, pl0, pl1;
    ph0.x = h0; ph0.y = h1; ph1.x = h2; ph1.y = h3;
    pl0.x = l0; pl0.y = l1; pl1.x = l2; pl1.y = l3;
    uint2 uh, ul;
    uh.x = *reinterpret_cast<uint32_t*>(&ph0);
    uh.y = *reinterpret_cast<uint32_t*>(&ph1);
    ul.x = *reinterpret_cast<uint32_t*>(&pl0);
    ul.y = *reinterpret_cast<uint32_t*>(&pl1);
    *reinterpret_cast<uint2*>(hi + off) = uh;
    *reinterpret_cast<uint2*>(lo + off) = ul;
}

static __device__ __forceinline__ void store_split2(
    __nv_bfloat16* __restrict__ hi, __nv_bfloat16* __restrict__ lo,
    size_t off, float x, float y)
{
    __nv_bfloat16 h0 = __float2bfloat16(x), h1 = __float2bfloat16(y);
    __nv_bfloat162 ph, pl;
    ph.x = h0; ph.y = h1;
    pl.x = __float2bfloat16(x - __bfloat162float(h0));
    pl.y = __float2bfloat16(y - __bfloat162float(h1));
    *reinterpret_cast<__nv_bfloat162*>(hi + off) = ph;
    *reinterpret_cast<__nv_bfloat162*>(lo + off) = pl;
}

// elementwise split: X[n] -> hi/lo (row-major preserved)
__global__ void __launch_bounds__(256) split_k(
    const float* __restrict__ X, __nv_bfloat16* __restrict__ hi,
    __nv_bfloat16* __restrict__ lo, int n4)
{
    int i = blockIdx.x * 256 + threadIdx.x;
    if (i < n4) {
        float4 v = reinterpret_cast<const float4*>(X)[i];
        store_split4(hi, lo, (size_t)i * 4, v);
    }
}

// transpose + split: W[K,N] -> Thi/Tlo[N,K]
__global__ void __launch_bounds__(256) tsplit_k(
    const float* __restrict__ W, __nv_bfloat16* __restrict__ Thi,
    __nv_bfloat16* __restrict__ Tlo, int K, int N)
{
    __shared__ float t[32][33];
    const int n0 = blockIdx.x * 32, k0 = blockIdx.y * 32;
    const int tx = threadIdx.x, ty = threadIdx.y;   // (32, 8)
#pragma unroll
    for (int j = 0; j < 32; j += 8)
        t[ty + j][tx] = W[(size_t)(k0 + ty + j) * N + n0 + tx];
    __syncthreads();
#pragma unroll
    for (int j = 0; j < 32; j += 8) {
        float v = t[tx][ty + j];
        size_t o = (size_t)(n0 + ty + j) * K + k0 + tx;
        __nv_bfloat16 h = __float2bfloat16(v);
        Thi[o] = h;
        Tlo[o] = __float2bfloat16(v - __bfloat162float(h));
    }
}

// ---------------- mma.sync split-bf16 GEMM ----------------------------------
// C[M,N] = (Ahi+Alo)[M,K] @ (Bhi+Blo)^T, B* stored [N,K] row-major.
// CTA 128x128, 8 warps (warp tile 32x64), K-chunk 32, cp.async double buffer.
// SMEM stage (40960 B): Ah | Al | Bh | Bl, each 128 rows x 40 bf16 (80 B stride).
#define STG   40960
#define AOFF  0
#define ALOFF 10240
#define BOFF  20480
#define BLOFF 30720
#define TGEMM_SMEM (2 * STG)

static __device__ __forceinline__ void load_stage(
    uint32_t smb, int stage,
    const __nv_bfloat16* __restrict__ Ah, const __nv_bfloat16* __restrict__ Al,
    const __nv_bfloat16* __restrict__ Bh, const __nv_bfloat16* __restrict__ Bl,
    int rowBase, int colBase, int K, int kt, int tid)
{
    const uint32_t sb = smb + stage * STG;
#pragma unroll
    for (int i = 0; i < 2; i++) {
        int idx = tid + i * 256;         // 0..511
        int r = idx >> 2;                // 0..127
        int kb = (idx & 3) * 8;          // 0,8,16,24
        uint32_t so = sb + (uint32_t)(r * 80 + kb * 2);
        size_t ga = (size_t)(rowBase + r) * K + kt + kb;
        size_t gb = (size_t)(colBase + r) * K + kt + kb;
        CP16(so + AOFF,  Ah + ga);
        CP16(so + ALOFF, Al + ga);
        CP16(so + BOFF,  Bh + gb);
        CP16(so + BLOFF, Bl + gb);
    }
}

template <bool BIAS, bool RELU, bool RES, bool OSPLIT>
__global__ void __launch_bounds__(256, 2) tgemm_k(
    const __nv_bfloat16* __restrict__ Ah, const __nv_bfloat16* __restrict__ Al,
    const __nv_bfloat16* __restrict__ Bh, const __nv_bfloat16* __restrict__ Bl,
    const float* __restrict__ bias, const float* __restrict__ res,
    float* __restrict__ C, __nv_bfloat16* __restrict__ Chi,
    __nv_bfloat16* __restrict__ Clo, int N, int K)
{
    extern __shared__ char sm[];
    const uint32_t smb = s2u(sm);
    const int tid = threadIdx.x;
    const int wid = tid >> 5, lane = tid & 31;
    const int m_base = (wid & 3) * 32;       // warp M offset (0..96)
    const int n_base = (wid >> 2) * 64;      // warp N offset (0 or 64)
    const int rowBase = blockIdx.y * 128, colBase = blockIdx.x * 128;

    float acc[2][8][4];
#pragma unroll
    for (int mf = 0; mf < 2; mf++)
#pragma unroll
        for (int nf = 0; nf < 8; nf++)
#pragma unroll
            for (int j = 0; j < 4; j++) acc[mf][nf][j] = 0.f;

    // per-thread ldmatrix byte offsets (within a stage)
    const uint32_t aOff = (uint32_t)((m_base + (lane & 15)) * 80 + (lane >> 4) * 16);
    const int bRow = (lane & 7) + ((lane >> 4) & 1) * 8;
    const uint32_t bOff = (uint32_t)((n_base + bRow) * 80 + ((lane >> 3) & 1) * 16);

    const int NC = K / 32;
    load_stage(smb, 0, Ah, Al, Bh, Bl, rowBase, colBase, K, 0, tid);
    CP_COMMIT();

    for (int c = 0; c < NC; ++c) {
        if (c + 1 < NC) {
            load_stage(smb, (c + 1) & 1, Ah, Al, Bh, Bl,
                       rowBase, colBase, K, (c + 1) * 32, tid);
            CP_COMMIT();
            CP_WAIT1();
        } else {
            CP_WAIT0();
        }
        __syncthreads();

        const uint32_t sb = smb + (uint32_t)(c & 1) * STG;
#pragma unroll
        for (int ks = 0; ks < 2; ks++) {
            uint32_t ah[2][4], al[2][4];
#pragma unroll
            for (int mf = 0; mf < 2; mf++) {
                ldsm4(ah[mf], sb + AOFF  + aOff + (uint32_t)(mf * 16 * 80 + ks * 32));
                ldsm4(al[mf], sb + ALOFF + aOff + (uint32_t)(mf * 16 * 80 + ks * 32));
            }
#pragma unroll
            for (int nf = 0; nf < 4; nf++) {
                uint32_t bh4[4], bl4[4];
                ldsm4(bh4, sb + BOFF  + bOff + (uint32_t)(nf * 16 * 80 + ks * 32));
                ldsm4(bl4, sb + BLOFF + bOff + (uint32_t)(nf * 16 * 80 + ks * 32));
#pragma unroll
                for (int mf = 0; mf < 2; mf++) {
                    mma16816(acc[mf][nf * 2],     ah[mf], bh4);
                    mma16816(acc[mf][nf * 2],     ah[mf], bl4);
                    mma16816(acc[mf][nf * 2],     al[mf], bh4);
                    mma16816(acc[mf][nf * 2 + 1], ah[mf], bh4 + 2);
                    mma16816(acc[mf][nf * 2 + 1], ah[mf], bl4 + 2);
                    mma16816(acc[mf][nf * 2 + 1], al[mf], bh4 + 2);
                }
            }
        }
        __syncthreads();
    }

    // epilogue
    const int group = lane >> 2, tig = lane & 3;
#pragma unroll
    for (int mf = 0; mf < 2; mf++) {
#pragma unroll
        for (int nf = 0; nf < 8; nf++) {
            const int c0 = colBase + n_base + nf * 8 + tig * 2;
            float bx = 0.f, by = 0.f;
            if (BIAS) {
                float2 bb = *reinterpret_cast<const float2*>(bias + c0);
                bx = bb.x; by = bb.y;
            }
#pragma unroll
            for (int half = 0; half < 2; half++) {
                const int r = rowBase + m_base + mf * 16 + group + half * 8;
                float ox = acc[mf][nf][half * 2 + 0];
                float oy = acc[mf][nf][half * 2 + 1];
                if (BIAS) { ox += bx; oy += by; }
                if (RES) {
                    float2 rr = *reinterpret_cast<const float2*>(
                        res + (size_t)r * N + c0);
                    ox += rr.x; oy += rr.y;
                }
                if (RELU) { ox = fmaxf(ox, 0.f); oy = fmaxf(oy, 0.f); }
                if (OSPLIT) {
                    store_split2(Chi, Clo, (size_t)r * N + c0, ox, oy);
                } else {
                    float2 o2; o2.x = ox; o2.y = oy;
                    *reinterpret_cast<float2*>(C + (size_t)r * N + c0) = o2;
                }
            }
        }
    }
}

// ---------------- flash attention (fp32, DK=64), writes split bf16 ----------
__global__ void __launch_bounds__(256) attn_k(
    const float* __restrict__ Q, const float* __restrict__ K,
    const float* __restrict__ V,
    __nv_bfloat16* __restrict__ Ohi, __nv_bfloat16* __restrict__ Olo)
{
    extern __shared__ float smf[];
    float* Qst = smf;                 // [dk][q]    64*128
    float* Kst = Qst + 64 * 128;      // [dk][key]  64*64
    float* Vs  = Kst + 64 * 64;       // [key][dk]  64*64
    float* Pst = Vs  + 64 * 64;       // [key][q]   64*128

    const int tid = threadIdx.x;
    const int tx = tid & 15;
    const int ty = tid >> 4;
    const int qBase = blockIdx.x * 128;
    const int h = blockIdx.y;
    const int b = blockIdx.z;
    const size_t base = (size_t)b * Sv * Dv + (size_t)h * DKv;

#pragma unroll
    for (int i = 0; i < 8; i++) {
        int f4 = tid + i * 256;
        int qr = f4 >> 4;
        int qc = (f4 & 15) * 4;
        float4 v = *reinterpret_cast<const float4*>(
            &Q[base + (size_t)(qBase + qr) * Dv + qc]);
        Qst[(qc + 0) * 128 + qr] = v.x * 0.125f;
        Qst[(qc + 1) * 128 + qr] = v.y * 0.125f;
        Qst[(qc + 2) * 128 + qr] = v.z * 0.125f;
        Qst[(qc + 3) * 128 + qr] = v.w * 0.125f;
    }

    float m[8], l[8], o[8][4];
#pragma unroll
    for (int i = 0; i < 8; i++) {
        m[i] = -1e30f; l[i] = 0.f;
#pragma unroll
        for (int j = 0; j < 4; j++) o[i][j] = 0.f;
    }

    for (int kt = 0; kt < Sv; kt += 64) {
        __syncthreads();
#pragma unroll
        for (int i = 0; i < 4; i++) {
            int f4 = tid + i * 256;
            int kr = f4 >> 4;
            int kc = (f4 & 15) * 4;
            float4 kv = *reinterpret_cast<const float4*>(
                &K[base + (size_t)(kt + kr) * Dv + kc]);
            Kst[(kc + 0) * 64 + kr] = kv.x;
            Kst[(kc + 1) * 64 + kr] = kv.y;
            Kst[(kc + 2) * 64 + kr] = kv.z;
            Kst[(kc + 3) * 64 + kr] = kv.w;
            float4 vv = *reinterpret_cast<const float4*>(
                &V[base + (size_t)(kt + kr) * Dv + kc]);
            *reinterpret_cast<float4*>(&Vs[kr * 64 + kc]) = vv;
        }
        __syncthreads();

        float s[8][4];
#pragma unroll
        for (int i = 0; i < 8; i++)
#pragma unroll
            for (int j = 0; j < 4; j++) s[i][j] = 0.f;
#pragma unroll
        for (int k = 0; k < 64; k++) {
            float a[8], bb[4];
            *reinterpret_cast<float4*>(&a[0]) = *reinterpret_cast<float4*>(&Qst[k * 128 + ty * 8]);
            *reinterpret_cast<float4*>(&a[4]) = *reinterpret_cast<float4*>(&Qst[k * 128 + ty * 8 + 4]);
            *reinterpret_cast<float4*>(&bb[0]) = *reinterpret_cast<float4*>(&Kst[k * 64 + tx * 4]);
#pragma unroll
            for (int i = 0; i < 8; i++)
#pragma unroll
                for (int j = 0; j < 4; j++)
                    s[i][j] = fmaf(a[i], bb[j], s[i][j]);
        }

#pragma unroll
        for (int i = 0; i < 8; i++) {
            float mi = fmaxf(fmaxf(s[i][0], s[i][1]), fmaxf(s[i][2], s[i][3]));
#pragma unroll
            for (int d = 1; d < 16; d <<= 1)
                mi = fmaxf(mi, __shfl_xor_sync(0xffffffffu, mi, d));
            float mn = fmaxf(m[i], mi);
            float corr = __expf(m[i] - mn);
            m[i] = mn;
            float ls = 0.f;
#pragma unroll
            for (int j = 0; j < 4; j++) {
                s[i][j] = __expf(s[i][j] - mn);
                ls += s[i][j];
            }
#pragma unroll
            for (int d = 1; d < 16; d <<= 1)
                ls += __shfl_xor_sync(0xffffffffu, ls, d);
            l[i] = l[i] * corr + ls;
#pragma unroll
            for (int j = 0; j < 4; j++) o[i][j] *= corr;
        }

#pragma unroll
        for (int i = 0; i < 8; i++)
#pragma unroll
            for (int j = 0; j < 4; j++)
                Pst[(tx * 4 + j) * 128 + ty * 8 + i] = s[i][j];
        __syncthreads();

#pragma unroll
        for (int k = 0; k < 64; k++) {
            float a[8], bb[4];
            *reinterpret_cast<float4*>(&a[0]) = *reinterpret_cast<float4*>(&Pst[k * 128 + ty * 8]);
            *reinterpret_cast<float4*>(&a[4]) = *reinterpret_cast<float4*>(&Pst[k * 128 + ty * 8 + 4]);
            *reinterpret_cast<float4*>(&bb[0]) = *reinterpret_cast<float4*>(&Vs[k * 64 + tx * 4]);
#pragma unroll
            for (int i = 0; i < 8; i++)
#pragma unroll
                for (int j = 0; j < 4; j++)
                    o[i][j] = fmaf(a[i], bb[j], o[i][j]);
        }
    }

#pragma unroll
    for (int i = 0; i < 8; i++) {
        float inv = 1.f / l[i];
        float4 ov;
        ov.x = o[i][0] * inv; ov.y = o[i][1] * inv;
        ov.z = o[i][2] * inv; ov.w = o[i][3] * inv;
        size_t off = base + (size_t)(qBase + ty * 8 + i) * Dv + tx * 4;
        store_split4(Ohi, Olo, off, ov);
    }
}

// ---------------- layernorm (ddof=1, scalar gamma/beta) ---------------------
template <bool SPLIT>
__global__ void __launch_bounds__(256) ln_k(
    const float* __restrict__ X, float* __restrict__ Y,
    __nv_bfloat16* __restrict__ Yh, __nv_bfloat16* __restrict__ Yl,
    const float* __restrict__ gamma, const float* __restrict__ beta)
{
    __shared__ float sh[64];
    const int row = blockIdx.x;
    const int tid = threadIdx.x;
    const float4 v = *reinterpret_cast<const float4*>(X + (size_t)row * Dv + tid * 4);
    float s = v.x + v.y + v.z + v.w;
    float sq = fmaf(v.x, v.x, fmaf(v.y, v.y, fmaf(v.z, v.z, v.w * v.w)));
#pragma unroll
    for (int d = 16; d > 0; d >>= 1) {
        s  += __shfl_xor_sync(0xffffffffu, s, d);
        sq += __shfl_xor_sync(0xffffffffu, sq, d);
    }
    const int w = tid >> 5, lane = tid & 31;
    if (lane == 0) { sh[w] = s; sh[32 + w] = sq; }
    __syncthreads();
    if (tid == 0) {
        float S = 0.f, SQ = 0.f;
        for (int i = 0; i < 8; i++) { S += sh[i]; SQ += sh[32 + i]; }
        sh[48] = S; sh[49] = SQ;
    }
    __syncthreads();
    const float S = sh[48], SQ = sh[49];
    const float mean = S * (1.f / 1024.f);
    const float var = (SQ - 1024.f * mean * mean) * (1.f / 1023.f);
    const float scale = gamma[0] / sqrtf(var + 1e-5f);
    const float be = beta[0];
    float4 ov;
    ov.x = (v.x - mean) * scale + be;
    ov.y = (v.y - mean) * scale + be;
    ov.z = (v.z - mean) * scale + be;
    ov.w = (v.w - mean) * scale + be;
    *reinterpret_cast<float4*>(Y + (size_t)row * Dv + tid * 4) = ov;
    if (SPLIT) store_split4(Yh, Yl, (size_t)row * Dv + tid * 4, ov);
}

// ---------------- launch ----------------------------------------------------
extern "C" void kernel_launch(void* const* d_in, const int* in_sizes, int n_in,
                              void* d_out, int out_size)
{
    (void)in_sizes; (void)n_in; (void)out_size;
    const float* x      = (const float*)d_in[0];
    const float* wq     = (const float*)d_in[2];
    const float* wk     = (const float*)d_in[3];
    const float* wv     = (const float*)d_in[4];
    const float* wo     = (const float*)d_in[5];
    const float* w1     = (const float*)d_in[6];
    const float* b1     = (const float*)d_in[7];
    const float* w2     = (const float*)d_in[8];
    const float* b2     = (const float*)d_in[9];
    const float* gamma1 = (const float*)d_in[10];
    const float* beta1  = (const float*)d_in[11];
    const float* gamma2 = (const float*)d_in[12];
    const float* beta2  = (const float*)d_in[13];
    float* out = (float*)d_out;

    float *q, *k, *v, *x1, *y;
    __nv_bfloat16 *xh, *xl, *ah, *al, *x1h, *x1l, *hh, *hl;
    __nv_bfloat16 *wqh, *wql, *wkh, *wkl, *wvh, *wvl, *woh, *wol;
    __nv_bfloat16 *w1h, *w1l, *w2h, *w2l;
    cudaGetSymbolAddress((void**)&q,   g_q);
    cudaGetSymbolAddress((void**)&k,   g_k);
    cudaGetSymbolAddress((void**)&v,   g_v);
    cudaGetSymbolAddress((void**)&x1,  g_x1);
    cudaGetSymbolAddress((void**)&y,   g_y);
    cudaGetSymbolAddress((void**)&xh,  g_xh);
    cudaGetSymbolAddress((void**)&xl,  g_xl);
    cudaGetSymbolAddress((void**)&ah,  g_ah);
    cudaGetSymbolAddress((void**)&al,  g_al);
    cudaGetSymbolAddress((void**)&x1h, g_x1h);
    cudaGetSymbolAddress((void**)&x1l, g_x1l);
    cudaGetSymbolAddress((void**)&hh,  g_hh);
    cudaGetSymbolAddress((void**)&hl,  g_hl);
    cudaGetSymbolAddress((void**)&wqh, g_wqh);
    cudaGetSymbolAddress((void**)&wql, g_wql);
    cudaGetSymbolAddress((void**)&wkh, g_wkh);
    cudaGetSymbolAddress((void**)&wkl, g_wkl);
    cudaGetSymbolAddress((void**)&wvh, g_wvh);
    cudaGetSymbolAddress((void**)&wvl, g_wvl);
    cudaGetSymbolAddress((void**)&woh, g_woh);
    cudaGetSymbolAddress((void**)&wol, g_wol);
    cudaGetSymbolAddress((void**)&w1h, g_w1h);
    cudaGetSymbolAddress((void**)&w1l, g_w1l);
    cudaGetSymbolAddress((void**)&w2h, g_w2h);
    cudaGetSymbolAddress((void**)&w2l, g_w2l);

    cudaFuncSetAttribute(attn_k, cudaFuncAttributeMaxDynamicSharedMemorySize, 96 * 1024);
    cudaFuncSetAttribute(tgemm_k<false, false, false, false>,
                         cudaFuncAttributeMaxDynamicSharedMemorySize, TGEMM_SMEM);
    cudaFuncSetAttribute(tgemm_k<false, false, true, false>,
                         cudaFuncAttributeMaxDynamicSharedMemorySize, TGEMM_SMEM);
    cudaFuncSetAttribute(tgemm_k<true, true, false, true>,
                         cudaFuncAttributeMaxDynamicSharedMemorySize, TGEMM_SMEM);
    cudaFuncSetAttribute(tgemm_k<true, false, true, false>,
                         cudaFuncAttributeMaxDynamicSharedMemorySize, TGEMM_SMEM);

    const dim3 tb(32, 8);
    // weight transpose + split
    tsplit_k<<<dim3(Dv / 32, Dv / 32), tb>>>(wq, wqh, wql, Dv, Dv);
    tsplit_k<<<dim3(Dv / 32, Dv / 32), tb>>>(wk, wkh, wkl, Dv, Dv);
    tsplit_k<<<dim3(Dv / 32, Dv / 32), tb>>>(wv, wvh, wvl, Dv, Dv);
    tsplit_k<<<dim3(Dv / 32, Dv / 32), tb>>>(wo, woh, wol, Dv, Dv);
    tsplit_k<<<dim3(DFFv / 32, Dv / 32), tb>>>(w1, w1h, w1l, Dv, DFFv);
    tsplit_k<<<dim3(Dv / 32, DFFv / 32), tb>>>(w2, w2h, w2l, DFFv, Dv);
    // x split
    split_k<<<(Mv * Dv / 4 + 255) / 256, 256>>>(x, xh, xl, Mv * Dv / 4);

    // QKV projections (tensor cores via mma.sync)
    tgemm_k<false, false, false, false><<<dim3(8, 32), 256, TGEMM_SMEM>>>(
        xh, xl, wqh, wql, nullptr, nullptr, q, nullptr, nullptr, Dv, Dv);
    tgemm_k<false, false, false, false><<<dim3(8, 32), 256, TGEMM_SMEM>>>(
        xh, xl, wkh, wkl, nullptr, nullptr, k, nullptr, nullptr, Dv, Dv);
    tgemm_k<false, false, false, false><<<dim3(8, 32), 256, TGEMM_SMEM>>>(
        xh, xl, wvh, wvl, nullptr, nullptr, v, nullptr, nullptr, Dv, Dv);

    // attention (SIMT fp32), emits split bf16 output
    attn_k<<<dim3(Sv / 128, Hv, Bv), 256, 96 * 1024>>>(q, k, v, ah, al);

    // O projection + residual(x), LN1 (emits split bf16 x1)
    tgemm_k<false, false, true, false><<<dim3(8, 32), 256, TGEMM_SMEM>>>(
        ah, al, woh, wol, nullptr, x, y, nullptr, nullptr, Dv, Dv);
    ln_k<true><<<Mv, 256>>>(y, x1, x1h, x1l, gamma1, beta1);

    // FFN1 (bias + relu), output directly as split bf16
    tgemm_k<true, true, false, true><<<dim3(32, 32), 256, TGEMM_SMEM>>>(
        x1h, x1l, w1h, w1l, b1, nullptr, nullptr, hh, hl, DFFv, Dv);
    // FFN2 (bias + residual x1), LN2
    tgemm_k<true, false, true, false><<<dim3(8, 32), 256, TGEMM_SMEM>>>(
        hh, hl, w2h, w2l, b2, x1, y, nullptr, nullptr, Dv, DFFv);
    ln_k<false><<<Mv, 256>>>(y, out, nullptr, nullptr, gamma2, beta2);
}

// round 5
// speedup vs baseline: 2.5545x; 1.5045x over previous
#include <cuda_runtime.h>
#include <cuda_bf16.h>
#include <cstdint>
#include <math.h>

#define Bv   2
#define Sv   2048
#define Dv   1024
#define Hv   16
#define DKv  64
#define DFFv 4096
#define Mv   (Bv * Sv)   // 4096 rows

// ---------------- scratch (device globals; no allocation allowed) ----------
__device__ float g_x1[Mv * Dv];
__device__ float g_y[Mv * Dv];

__device__ __nv_bfloat16 g_xh[Mv * Dv],  g_xl[Mv * Dv];
__device__ __nv_bfloat16 g_qh[Mv * Dv],  g_ql[Mv * Dv];
__device__ __nv_bfloat16 g_kh[Mv * Dv],  g_kl[Mv * Dv];
__device__ __nv_bfloat16 g_vh[Mv * Dv],  g_vl[Mv * Dv];
__device__ __nv_bfloat16 g_ah[Mv * Dv],  g_al[Mv * Dv];
__device__ __nv_bfloat16 g_x1h[Mv * Dv], g_x1l[Mv * Dv];
__device__ __nv_bfloat16 g_hh[(size_t)Mv * DFFv], g_hl[(size_t)Mv * DFFv];

__device__ __nv_bfloat16 g_wqh[Dv * Dv], g_wql[Dv * Dv];
__device__ __nv_bfloat16 g_wkh[Dv * Dv], g_wkl[Dv * Dv];
__device__ __nv_bfloat16 g_wvh[Dv * Dv], g_wvl[Dv * Dv];
__device__ __nv_bfloat16 g_woh[Dv * Dv], g_wol[Dv * Dv];
__device__ __nv_bfloat16 g_w1h[Dv * DFFv], g_w1l[Dv * DFFv];   // transposed: [DFF, D]
__device__ __nv_bfloat16 g_w2h[Dv * DFFv], g_w2l[Dv * DFFv];   // transposed: [D, DFF]

// ---------------- PTX helpers (base sm_80+ only; no tcgen05) ----------------
static __device__ __forceinline__ uint32_t s2u(const void* p) {
    uint32_t a;
    asm("{ .reg .u64 t; cvta.to.shared.u64 t, %1; cvt.u32.u64 %0, t; }"
        : "=r"(a) : "l"(p));
    return a;
}

static __device__ __forceinline__ void ldsm4(uint32_t* r, uint32_t addr) {
    asm volatile("ldmatrix.sync.aligned.m8n8.x4.shared.b16 {%0,%1,%2,%3}, [%4];"
        : "=r"(r[0]), "=r"(r[1]), "=r"(r[2]), "=r"(r[3]) : "r"(addr));
}

static __device__ __forceinline__ void mma16816(
    float* d, const uint32_t* a, const uint32_t* b)
{
    asm volatile("mma.sync.aligned.m16n8k16.row.col.f32.bf16.bf16.f32 "
        "{%0,%1,%2,%3}, {%4,%5,%6,%7}, {%8,%9}, {%0,%1,%2,%3};"
        : "+f"(d[0]), "+f"(d[1]), "+f"(d[2]), "+f"(d[3])
        : "r"(a[0]), "r"(a[1]), "r"(a[2]), "r"(a[3]), "r"(b[0]), "r"(b[1]));
}

#define CP16(dst, src) \
    asm volatile("cp.async.cg.shared.global [%0], [%1], 16;" \
                 :: "r"(dst), "l"(src))
#define CP_COMMIT() asm volatile("cp.async.commit_group;" ::: "memory")
#define CP_WAIT0()  asm volatile("cp.async.wait_group 0;" ::: "memory")
#define CP_WAIT1()  asm volatile("cp.async.wait_group 1;" ::: "memory")

// ---------------- fast exp on FMA pipe: pexp(s) = exp(s / 8) ----------------
// (the 1/sqrt(64) attention scale is folded into the log2(e)/8 constant)
static __device__ __forceinline__ float pexp(float s) {
    const float C = 0.125f * 1.4426950408889634f;
    s = fmaxf(s, -500.0f);                       // keep exponent math in range
    float yr = fmaf(s, C, 12582912.0f);          // round-to-nearest via magic
    int   n  = __float_as_int(yr) - 0x4B400000;  // integer part
    float nf = yr - 12582912.0f;
    float f  = fmaf(s, C, -nf);                  // f in [-0.5, 0.5]
    float p  = 0.0018775767f;
    p = fmaf(p, f, 0.0089893397f);
    p = fmaf(p, f, 0.0558026980f);
    p = fmaf(p, f, 0.2401597153f);
    p = fmaf(p, f, 0.6931471825f);
    p = fmaf(p, f, 1.0f);
    return __int_as_float(__float_as_int(p) + (n << 23));   // p * 2^n
}

// ---------------- bf16 hi/lo split helpers ----------------------------------
static __device__ __forceinline__ void store_split4(
    __nv_bfloat16* __restrict__ hi, __nv_bfloat16* __restrict__ lo,
    size_t off, float4 v)
{
    __nv_bfloat16 h0 = __float2bfloat16(v.x), h1 = __float2bfloat16(v.y);
    __nv_bfloat16 h2 = __float2bfloat16(v.z), h3 = __float2bfloat16(v.w);
    __nv_bfloat16 l0 = __float2bfloat16(v.x - __bfloat162float(h0));
    __nv_bfloat16 l1 = __float2bfloat16(v.y - __bfloat162float(h1));
    __nv_bfloat16 l2 = __float2bfloat16(v.z - __bfloat162float(h2));
    __nv_bfloat16 l3 = __float2bfloat16(v.w - __bfloat162float(h3));
    __nv_bfloat162 ph0, ph1, pl0, pl1;
    ph0.x = h0; ph0.y = h1; ph1.x = h2; ph1.y = h3;
    pl0.x = l0; pl0.y = l1; pl1.x = l2; pl1.y = l3;
    uint2 uh, ul;
    uh.x = *reinterpret_cast<uint32_t*>(&ph0);
    uh.y = *reinterpret_cast<uint32_t*>(&ph1);
    ul.x = *reinterpret_cast<uint32_t*>(&pl0);
    ul.y = *reinterpret_cast<uint32_t*>(&pl1);
    *reinterpret_cast<uint2*>(hi + off) = uh;
    *reinterpret_cast<uint2*>(lo + off) = ul;
}

static __device__ __forceinline__ void store_split2(
    __nv_bfloat16* __restrict__ hi, __nv_bfloat16* __restrict__ lo,
    size_t off, float x, float y)
{
    __nv_bfloat16 h0 = __float2bfloat16(x), h1 = __float2bfloat16(y);
    __nv_bfloat162 ph, pl;
    ph.x = h0; ph.y = h1;
    pl.x = __float2bfloat16(x - __bfloat162float(h0));
    pl.y = __float2bfloat16(y - __bfloat162float(h1));
    *reinterpret_cast<__nv_bfloat162*>(hi + off) = ph;
    *reinterpret_cast<__nv_bfloat162*>(lo + off) = pl;
}

static __device__ __forceinline__ void psplit(
    float x, float y, uint32_t& hi, uint32_t& lo)
{
    __nv_bfloat162 h, l;
    h.x = __float2bfloat16(x); h.y = __float2bfloat16(y);
    l.x = __float2bfloat16(x - __bfloat162float(h.x));
    l.y = __float2bfloat16(y - __bfloat162float(h.y));
    hi = *reinterpret_cast<uint32_t*>(&h);
    lo = *reinterpret_cast<uint32_t*>(&l);
}

// elementwise split: X[n] -> hi/lo (row-major preserved)
__global__ void __launch_bounds__(256) split_k(
    const float* __restrict__ X, __nv_bfloat16* __restrict__ hi,
    __nv_bfloat16* __restrict__ lo, int n4)
{
    int i = blockIdx.x * 256 + threadIdx.x;
    if (i < n4) {
        float4 v = reinterpret_cast<const float4*>(X)[i];
        store_split4(hi, lo, (size_t)i * 4, v);
    }
}

// transpose + split: W[K,N] -> Thi/Tlo[N,K]
__global__ void __launch_bounds__(256) tsplit_k(
    const float* __restrict__ W, __nv_bfloat16* __restrict__ Thi,
    __nv_bfloat16* __restrict__ Tlo, int K, int N)
{
    __shared__ float t[32][33];
    const int n0 = blockIdx.x * 32, k0 = blockIdx.y * 32;
    const int tx = threadIdx.x, ty = threadIdx.y;   // (32, 8)
#pragma unroll
    for (int j = 0; j < 32; j += 8)
        t[ty + j][tx] = W[(size_t)(k0 + ty + j) * N + n0 + tx];
    __syncthreads();
#pragma unroll
    for (int j = 0; j < 32; j += 8) {
        float v = t[tx][ty + j];
        size_t o = (size_t)(n0 + ty + j) * K + k0 + tx;
        __nv_bfloat16 h = __float2bfloat16(v);
        Thi[o] = h;
        Tlo[o] = __float2bfloat16(v - __bfloat162float(h));
    }
}

// ---------------- mma.sync split-bf16 GEMM (unchanged from R4) --------------
#define STG   40960
#define AOFF  0
#define ALOFF 10240
#define BOFF  20480
#define BLOFF 30720
#define TGEMM_SMEM (2 * STG)

static __device__ __forceinline__ void load_stage(
    uint32_t smb, int stage,
    const __nv_bfloat16* __restrict__ Ah, const __nv_bfloat16* __restrict__ Al,
    const __nv_bfloat16* __restrict__ Bh, const __nv_bfloat16* __restrict__ Bl,
    int rowBase, int colBase, int K, int kt, int tid)
{
    const uint32_t sb = smb + stage * STG;
#pragma unroll
    for (int i = 0; i < 2; i++) {
        int idx = tid + i * 256;         // 0..511
        int r = idx >> 2;                // 0..127
        int kb = (idx & 3) * 8;          // 0,8,16,24
        uint32_t so = sb + (uint32_t)(r * 80 + kb * 2);
        size_t ga = (size_t)(rowBase + r) * K + kt + kb;
        size_t gb = (size_t)(colBase + r) * K + kt + kb;
        CP16(so + AOFF,  Ah + ga);
        CP16(so + ALOFF, Al + ga);
        CP16(so + BOFF,  Bh + gb);
        CP16(so + BLOFF, Bl + gb);
    }
}

template <bool BIAS, bool RELU, bool RES, bool OSPLIT>
__global__ void __launch_bounds__(256, 2) tgemm_k(
    const __nv_bfloat16* __restrict__ Ah, const __nv_bfloat16* __restrict__ Al,
    const __nv_bfloat16* __restrict__ Bh, const __nv_bfloat16* __restrict__ Bl,
    const float* __restrict__ bias, const float* __restrict__ res,
    float* __restrict__ C, __nv_bfloat16* __restrict__ Chi,
    __nv_bfloat16* __restrict__ Clo, int N, int K)
{
    extern __shared__ char sm[];
    const uint32_t smb = s2u(sm);
    const int tid = threadIdx.x;
    const int wid = tid >> 5, lane = tid & 31;
    const int m_base = (wid & 3) * 32;
    const int n_base = (wid >> 2) * 64;
    const int rowBase = blockIdx.y * 128, colBase = blockIdx.x * 128;

    float acc[2][8][4];
#pragma unroll
    for (int mf = 0; mf < 2; mf++)
#pragma unroll
        for (int nf = 0; nf < 8; nf++)
#pragma unroll
            for (int j = 0; j < 4; j++) acc[mf][nf][j] = 0.f;

    const uint32_t aOff = (uint32_t)((m_base + (lane & 15)) * 80 + (lane >> 4) * 16);
    const int bRow = (lane & 7) + ((lane >> 4) & 1) * 8;
    const uint32_t bOff = (uint32_t)((n_base + bRow) * 80 + ((lane >> 3) & 1) * 16);

    const int NC = K / 32;
    load_stage(smb, 0, Ah, Al, Bh, Bl, rowBase, colBase, K, 0, tid);
    CP_COMMIT();

    for (int c = 0; c < NC; ++c) {
        if (c + 1 < NC) {
            load_stage(smb, (c + 1) & 1, Ah, Al, Bh, Bl,
                       rowBase, colBase, K, (c + 1) * 32, tid);
            CP_COMMIT();
            CP_WAIT1();
        } else {
            CP_WAIT0();
        }
        __syncthreads();

        const uint32_t sb = smb + (uint32_t)(c & 1) * STG;
#pragma unroll
        for (int ks = 0; ks < 2; ks++) {
            uint32_t ah[2][4], al[2][4];
#pragma unroll
            for (int mf = 0; mf < 2; mf++) {
                ldsm4(ah[mf], sb + AOFF  + aOff + (uint32_t)(mf * 16 * 80 + ks * 32));
                ldsm4(al[mf], sb + ALOFF + aOff + (uint32_t)(mf * 16 * 80 + ks * 32));
            }
#pragma unroll
            for (int nf = 0; nf < 4; nf++) {
                uint32_t bh4[4], bl4[4];
                ldsm4(bh4, sb + BOFF  + bOff + (uint32_t)(nf * 16 * 80 + ks * 32));
                ldsm4(bl4, sb + BLOFF + bOff + (uint32_t)(nf * 16 * 80 + ks * 32));
#pragma unroll
                for (int mf = 0; mf < 2; mf++) {
                    mma16816(acc[mf][nf * 2],     ah[mf], bh4);
                    mma16816(acc[mf][nf * 2],     ah[mf], bl4);
                    mma16816(acc[mf][nf * 2],     al[mf], bh4);
                    mma16816(acc[mf][nf * 2 + 1], ah[mf], bh4 + 2);
                    mma16816(acc[mf][nf * 2 + 1], ah[mf], bl4 + 2);
                    mma16816(acc[mf][nf * 2 + 1], al[mf], bh4 + 2);
                }
            }
        }
        __syncthreads();
    }

    const int group = lane >> 2, tig = lane & 3;
#pragma unroll
    for (int mf = 0; mf < 2; mf++) {
#pragma unroll
        for (int nf = 0; nf < 8; nf++) {
            const int c0 = colBase + n_base + nf * 8 + tig * 2;
            float bx = 0.f, by = 0.f;
            if (BIAS) {
                float2 bb = *reinterpret_cast<const float2*>(bias + c0);
                bx = bb.x; by = bb.y;
            }
#pragma unroll
            for (int half = 0; half < 2; half++) {
                const int r = rowBase + m_base + mf * 16 + group + half * 8;
                float ox = acc[mf][nf][half * 2 + 0];
                float oy = acc[mf][nf][half * 2 + 1];
                if (BIAS) { ox += bx; oy += by; }
                if (RES) {
                    float2 rr = *reinterpret_cast<const float2*>(
                        res + (size_t)r * N + c0);
                    ox += rr.x; oy += rr.y;
                }
                if (RELU) { ox = fmaxf(ox, 0.f); oy = fmaxf(oy, 0.f); }
                if (OSPLIT) {
                    store_split2(Chi, Clo, (size_t)r * N + c0, ox, oy);
                } else {
                    float2 o2; o2.x = ox; o2.y = oy;
                    *reinterpret_cast<float2*>(C + (size_t)r * N + c0) = o2;
                }
            }
        }
    }
}

// ---------------- tensor-core flash attention --------------------------------
// Block: 128 queries x 1 head; 8 warps x 16 query rows; 64-key chunks.
// smem (bf16, row stride 72 elems = 144 B, all byte offsets):
//   Qh @ 0      Ql @ 18432   (128 x 72 each)
//   Kh @ 36864  Kl @ 46080   (64 keys x 72)
//   Vth @ 55296 Vtl @ 64512  (64 d x 72, V TRANSPOSED at fill)
#define QHB 0
#define QLB 18432
#define KHB 36864
#define KLB 46080
#define VHB 55296
#define VLB 64512
#define ATT_SMEM 73728

__global__ void __launch_bounds__(256, 2) attn_tc_k(
    const __nv_bfloat16* __restrict__ Qh, const __nv_bfloat16* __restrict__ Ql,
    const __nv_bfloat16* __restrict__ Kh, const __nv_bfloat16* __restrict__ Kl,
    const __nv_bfloat16* __restrict__ Vh, const __nv_bfloat16* __restrict__ Vl,
    __nv_bfloat16* __restrict__ Ohi, __nv_bfloat16* __restrict__ Olo)
{
    extern __shared__ char sm[];
    const uint32_t smb = s2u(sm);
    const int tid = threadIdx.x;
    const int wid = tid >> 5, lane = tid & 31;
    const int group = lane >> 2, tig = lane & 3;
    const int qBase = blockIdx.x * 128;
    const int h = blockIdx.y, b = blockIdx.z;
    const size_t gbase = (size_t)b * Sv * Dv + (size_t)h * DKv;

    // Q fill (once): 128 rows x 64 elems, split hi/lo
#pragma unroll
    for (int i = 0; i < 4; i++) {
        int idx = tid + i * 256;          // 0..1023
        int r = idx >> 3;
        int c = (idx & 7) * 8;
        size_t g = gbase + (size_t)(qBase + r) * Dv + c;
        uint32_t so = (uint32_t)(r * 144 + c * 2);
        CP16(smb + QHB + so, Qh + g);
        CP16(smb + QLB + so, Ql + g);
    }
    CP_COMMIT();

    float m0 = -1e30f, m1 = -1e30f, l0 = 0.f, l1 = 0.f;
    float O[8][4];
#pragma unroll
    for (int nf = 0; nf < 8; nf++)
#pragma unroll
        for (int j = 0; j < 4; j++) O[nf][j] = 0.f;

    const uint32_t aOff = (uint32_t)((wid * 16 + (lane & 15)) * 144 + (lane >> 4) * 16);
    const int bRow = (lane & 7) + ((lane >> 4) & 1) * 8;
    const uint32_t bOff = (uint32_t)(bRow * 144 + ((lane >> 3) & 1) * 16);

    for (int kt = 0; kt < Sv; kt += 64) {
        __syncthreads();   // previous chunk's consumers done
        // K fill (cp.async): 64 rows x 64 elems
#pragma unroll
        for (int i = 0; i < 2; i++) {
            int idx = tid + i * 256;
            int r = idx >> 3;
            int c = (idx & 7) * 8;
            size_t g = gbase + (size_t)(kt + r) * Dv + c;
            uint32_t so = (uint32_t)(r * 144 + c * 2);
            CP16(smb + KHB + so, Kh + g);
            CP16(smb + KLB + so, Kl + g);
        }
        CP_COMMIT();
        // V fill TRANSPOSED (plain loads + scalar stores)
#pragma unroll
        for (int i = 0; i < 2; i++) {
            int idx = tid + i * 256;
            int key = idx & 63;
            int db = (idx >> 6) * 8;
            size_t g = gbase + (size_t)(kt + key) * Dv + db;
            uint4 hv = *reinterpret_cast<const uint4*>(Vh + g);
            uint4 lv = *reinterpret_cast<const uint4*>(Vl + g);
            const __nv_bfloat16* hp = reinterpret_cast<const __nv_bfloat16*>(&hv);
            const __nv_bfloat16* lp = reinterpret_cast<const __nv_bfloat16*>(&lv);
#pragma unroll
            for (int j = 0; j < 8; j++) {
                uint32_t so = (uint32_t)((db + j) * 144 + key * 2);
                *reinterpret_cast<__nv_bfloat16*>(sm + VHB + so) = hp[j];
                *reinterpret_cast<__nv_bfloat16*>(sm + VLB + so) = lp[j];
            }
        }
        CP_WAIT0();
        __syncthreads();

        // ---- S = Q @ K^T (raw scores; 1/8 folded into pexp) ----
        float S[8][4];
#pragma unroll
        for (int nf = 0; nf < 8; nf++)
#pragma unroll
            for (int j = 0; j < 4; j++) S[nf][j] = 0.f;
#pragma unroll
        for (int ks = 0; ks < 4; ks++) {
            uint32_t ah4[4], al4[4];
            ldsm4(ah4, smb + QHB + aOff + (uint32_t)(ks * 32));
            ldsm4(al4, smb + QLB + aOff + (uint32_t)(ks * 32));
#pragma unroll
            for (int nf2 = 0; nf2 < 4; nf2++) {
                uint32_t bh4[4], bl4[4];
                ldsm4(bh4, smb + KHB + bOff + (uint32_t)(nf2 * 16 * 144 + ks * 32));
                ldsm4(bl4, smb + KLB + bOff + (uint32_t)(nf2 * 16 * 144 + ks * 32));
                mma16816(S[nf2 * 2],     ah4, bh4);
                mma16816(S[nf2 * 2],     ah4, bl4);
                mma16816(S[nf2 * 2],     al4, bh4);
                mma16816(S[nf2 * 2 + 1], ah4, bh4 + 2);
                mma16816(S[nf2 * 2 + 1], ah4, bl4 + 2);
                mma16816(S[nf2 * 2 + 1], al4, bh4 + 2);
            }
        }

        // ---- online softmax (rows r0 = group, r1 = group+8 of warp tile) ----
        float mx0 = -1e30f, mx1 = -1e30f;
#pragma unroll
        for (int nf = 0; nf < 8; nf++) {
            mx0 = fmaxf(mx0, fmaxf(S[nf][0], S[nf][1]));
            mx1 = fmaxf(mx1, fmaxf(S[nf][2], S[nf][3]));
        }
        mx0 = fmaxf(mx0, __shfl_xor_sync(0xffffffffu, mx0, 1));
        mx0 = fmaxf(mx0, __shfl_xor_sync(0xffffffffu, mx0, 2));
        mx1 = fmaxf(mx1, __shfl_xor_sync(0xffffffffu, mx1, 1));
        mx1 = fmaxf(mx1, __shfl_xor_sync(0xffffffffu, mx1, 2));
        const float mn0 = fmaxf(m0, mx0), mn1 = fmaxf(m1, mx1);
        const float cr0 = pexp(m0 - mn0), cr1 = pexp(m1 - mn1);
        m0 = mn0; m1 = mn1;
        float s0 = 0.f, s1 = 0.f;
#pragma unroll
        for (int nf = 0; nf < 8; nf++) {
            S[nf][0] = pexp(S[nf][0] - mn0);
            S[nf][1] = pexp(S[nf][1] - mn0);
            S[nf][2] = pexp(S[nf][2] - mn1);
            S[nf][3] = pexp(S[nf][3] - mn1);
            s0 += S[nf][0] + S[nf][1];
            s1 += S[nf][2] + S[nf][3];
        }
        s0 += __shfl_xor_sync(0xffffffffu, s0, 1);
        s0 += __shfl_xor_sync(0xffffffffu, s0, 2);
        s1 += __shfl_xor_sync(0xffffffffu, s1, 1);
        s1 += __shfl_xor_sync(0xffffffffu, s1, 2);
        l0 = l0 * cr0 + s0;
        l1 = l1 * cr1 + s1;
#pragma unroll
        for (int nf = 0; nf < 8; nf++) {
            O[nf][0] *= cr0; O[nf][1] *= cr0;
            O[nf][2] *= cr1; O[nf][3] *= cr1;
        }

        // ---- O += P @ V  (P split hi/lo, V split from smem transposed) ----
#pragma unroll
        for (int kf = 0; kf < 4; kf++) {
            uint32_t aPh[4], aPl[4];
            psplit(S[2 * kf][0],     S[2 * kf][1],     aPh[0], aPl[0]);
            psplit(S[2 * kf][2],     S[2 * kf][3],     aPh[1], aPl[1]);
            psplit(S[2 * kf + 1][0], S[2 * kf + 1][1], aPh[2], aPl[2]);
            psplit(S[2 * kf + 1][2], S[2 * kf + 1][3], aPh[3], aPl[3]);
#pragma unroll
            for (int nf2 = 0; nf2 < 4; nf2++) {
                uint32_t bvh[4], bvl[4];
                ldsm4(bvh, smb + VHB + bOff + (uint32_t)(nf2 * 16 * 144 + kf * 32));
                ldsm4(bvl, smb + VLB + bOff + (uint32_t)(nf2 * 16 * 144 + kf * 32));
                mma16816(O[nf2 * 2],     aPh, bvh);
                mma16816(O[nf2 * 2],     aPh, bvl);
                mma16816(O[nf2 * 2],     aPl, bvh);
                mma16816(O[nf2 * 2 + 1], aPh, bvh + 2);
                mma16816(O[nf2 * 2 + 1], aPh, bvl + 2);
                mma16816(O[nf2 * 2 + 1], aPl, bvh + 2);
            }
        }
    }

    // ---- normalize + write split bf16 ----
    const float inv0 = 1.f / l0, inv1 = 1.f / l1;
    const int r0 = qBase + wid * 16 + group;
#pragma unroll
    for (int nf = 0; nf < 8; nf++) {
        const int col = nf * 8 + tig * 2;
        size_t off0 = gbase + (size_t)r0 * Dv + col;
        size_t off1 = gbase + (size_t)(r0 + 8) * Dv + col;
        store_split2(Ohi, Olo, off0, O[nf][0] * inv0, O[nf][1] * inv0);
        store_split2(Ohi, Olo, off1, O[nf][2] * inv1, O[nf][3] * inv1);
    }
}

// ---------------- layernorm (ddof=1, scalar gamma/beta) ---------------------
template <bool SPLIT>
__global__ void __launch_bounds__(256) ln_k(
    const float* __restrict__ X, float* __restrict__ Y,
    __nv_bfloat16* __restrict__ Yh, __nv_bfloat16* __restrict__ Yl,
    const float* __restrict__ gamma, const float* __restrict__ beta)
{
    __shared__ float sh[64];
    const int row = blockIdx.x;
    const int tid = threadIdx.x;
    const float4 v = *reinterpret_cast<const float4*>(X + (size_t)row * Dv + tid * 4);
    float s = v.x + v.y + v.z + v.w;
    float sq = fmaf(v.x, v.x, fmaf(v.y, v.y, fmaf(v.z, v.z, v.w * v.w)));
#pragma unroll
    for (int d = 16; d > 0; d >>= 1) {
        s  += __shfl_xor_sync(0xffffffffu, s, d);
        sq += __shfl_xor_sync(0xffffffffu, sq, d);
    }
    const int w = tid >> 5, lane = tid & 31;
    if (lane == 0) { sh[w] = s; sh[32 + w] = sq; }
    __syncthreads();
    if (tid == 0) {
        float S = 0.f, SQ = 0.f;
        for (int i = 0; i < 8; i++) { S += sh[i]; SQ += sh[32 + i]; }
        sh[48] = S; sh[49] = SQ;
    }
    __syncthreads();
    const float S = sh[48], SQ = sh[49];
    const float mean = S * (1.f / 1024.f);
    const float var = (SQ - 1024.f * mean * mean) * (1.f / 1023.f);
    const float scale = gamma[0] / sqrtf(var + 1e-5f);
    const float be = beta[0];
    float4 ov;
    ov.x = (v.x - mean) * scale + be;
    ov.y = (v.y - mean) * scale + be;
    ov.z = (v.z - mean) * scale + be;
    ov.w = (v.w - mean) * scale + be;
    *reinterpret_cast<float4*>(Y + (size_t)row * Dv + tid * 4) = ov;
    if (SPLIT) store_split4(Yh, Yl, (size_t)row * Dv + tid * 4, ov);
}

// ---------------- launch ----------------------------------------------------
extern "C" void kernel_launch(void* const* d_in, const int* in_sizes, int n_in,
                              void* d_out, int out_size)
{
    (void)in_sizes; (void)n_in; (void)out_size;
    const float* x      = (const float*)d_in[0];
    const float* wq     = (const float*)d_in[2];
    const float* wk     = (const float*)d_in[3];
    const float* wv     = (const float*)d_in[4];
    const float* wo     = (const float*)d_in[5];
    const float* w1     = (const float*)d_in[6];
    const float* b1     = (const float*)d_in[7];
    const float* w2     = (const float*)d_in[8];
    const float* b2     = (const float*)d_in[9];
    const float* gamma1 = (const float*)d_in[10];
    const float* beta1  = (const float*)d_in[11];
    const float* gamma2 = (const float*)d_in[12];
    const float* beta2  = (const float*)d_in[13];
    float* out = (float*)d_out;

    float *x1, *y;
    __nv_bfloat16 *xh, *xl, *qh, *ql, *kh, *kl, *vh, *vl, *ah, *al;
    __nv_bfloat16 *x1h, *x1l, *hh, *hl;
    __nv_bfloat16 *wqh, *wql, *wkh, *wkl, *wvh, *wvl, *woh, *wol;
    __nv_bfloat16 *w1h, *w1l, *w2h, *w2l;
    cudaGetSymbolAddress((void**)&x1,  g_x1);
    cudaGetSymbolAddress((void**)&y,   g_y);
    cudaGetSymbolAddress((void**)&xh,  g_xh);
    cudaGetSymbolAddress((void**)&xl,  g_xl);
    cudaGetSymbolAddress((void**)&qh,  g_qh);
    cudaGetSymbolAddress((void**)&ql,  g_ql);
    cudaGetSymbolAddress((void**)&kh,  g_kh);
    cudaGetSymbolAddress((void**)&kl,  g_kl);
    cudaGetSymbolAddress((void**)&vh,  g_vh);
    cudaGetSymbolAddress((void**)&vl,  g_vl);
    cudaGetSymbolAddress((void**)&ah,  g_ah);
    cudaGetSymbolAddress((void**)&al,  g_al);
    cudaGetSymbolAddress((void**)&x1h, g_x1h);
    cudaGetSymbolAddress((void**)&x1l, g_x1l);
    cudaGetSymbolAddress((void**)&hh,  g_hh);
    cudaGetSymbolAddress((void**)&hl,  g_hl);
    cudaGetSymbolAddress((void**)&wqh, g_wqh);
    cudaGetSymbolAddress((void**)&wql, g_wql);
    cudaGetSymbolAddress((void**)&wkh, g_wkh);
    cudaGetSymbolAddress((void**)&wkl, g_wkl);
    cudaGetSymbolAddress((void**)&wvh, g_wvh);
    cudaGetSymbolAddress((void**)&wvl, g_wvl);
    cudaGetSymbolAddress((void**)&woh, g_woh);
    cudaGetSymbolAddress((void**)&wol, g_wol);
    cudaGetSymbolAddress((void**)&w1h, g_w1h);
    cudaGetSymbolAddress((void**)&w1l, g_w1l);
    cudaGetSymbolAddress((void**)&w2h, g_w2h);
    cudaGetSymbolAddress((void**)&w2l, g_w2l);

    cudaFuncSetAttribute(attn_tc_k, cudaFuncAttributeMaxDynamicSharedMemorySize, ATT_SMEM);
    cudaFuncSetAttribute(tgemm_k<false, false, false, true>,
                         cudaFuncAttributeMaxDynamicSharedMemorySize, TGEMM_SMEM);
    cudaFuncSetAttribute(tgemm_k<false, false, true, false>,
                         cudaFuncAttributeMaxDynamicSharedMemorySize, TGEMM_SMEM);
    cudaFuncSetAttribute(tgemm_k<true, true, false, true>,
                         cudaFuncAttributeMaxDynamicSharedMemorySize, TGEMM_SMEM);
    cudaFuncSetAttribute(tgemm_k<true, false, true, false>,
                         cudaFuncAttributeMaxDynamicSharedMemorySize, TGEMM_SMEM);

    const dim3 tb(32, 8);
    // weight transpose + split
    tsplit_k<<<dim3(Dv / 32, Dv / 32), tb>>>(wq, wqh, wql, Dv, Dv);
    tsplit_k<<<dim3(Dv / 32, Dv / 32), tb>>>(wk, wkh, wkl, Dv, Dv);
    tsplit_k<<<dim3(Dv / 32, Dv / 32), tb>>>(wv, wvh, wvl, Dv, Dv);
    tsplit_k<<<dim3(Dv / 32, Dv / 32), tb>>>(wo, woh, wol, Dv, Dv);
    tsplit_k<<<dim3(DFFv / 32, Dv / 32), tb>>>(w1, w1h, w1l, Dv, DFFv);
    tsplit_k<<<dim3(Dv / 32, DFFv / 32), tb>>>(w2, w2h, w2l, DFFv, Dv);
    // x split
    split_k<<<(Mv * Dv / 4 + 255) / 256, 256>>>(x, xh, xl, Mv * Dv / 4);

    // QKV projections (emit split bf16 directly; no fp32 round trip)
    tgemm_k<false, false, false, true><<<dim3(8, 32), 256, TGEMM_SMEM>>>(
        xh, xl, wqh, wql, nullptr, nullptr, nullptr, qh, ql, Dv, Dv);
    tgemm_k<false, false, false, true><<<dim3(8, 32), 256, TGEMM_SMEM>>>(
        xh, xl, wkh, wkl, nullptr, nullptr, nullptr, kh, kl, Dv, Dv);
    tgemm_k<false, false, false, true><<<dim3(8, 32), 256, TGEMM_SMEM>>>(
        xh, xl, wvh, wvl, nullptr, nullptr, nullptr, vh, vl, Dv, Dv);

    // tensor-core flash attention, emits split bf16
    attn_tc_k<<<dim3(Sv / 128, Hv, Bv), 256, ATT_SMEM>>>(
        qh, ql, kh, kl, vh, vl, ah, al);

    // O projection + residual(x), LN1 (emits split bf16 x1)
    tgemm_k<false, false, true, false><<<dim3(8, 32), 256, TGEMM_SMEM>>>(
        ah, al, woh, wol, nullptr, x, y, nullptr, nullptr, Dv, Dv);
    ln_k<true><<<Mv, 256>>>(y, x1, x1h, x1l, gamma1, beta1);

    // FFN1 (bias + relu), output directly as split bf16
    tgemm_k<true, true, false, true><<<dim3(32, 32), 256, TGEMM_SMEM>>>(
        x1h, x1l, w1h, w1l, b1, nullptr, nullptr, hh, hl, DFFv, Dv);
    // FFN2 (bias + residual x1), LN2
    tgemm_k<true, false, true, false><<<dim3(8, 32), 256, TGEMM_SMEM>>>(
        hh, hl, w2h, w2l, b2, x1, y, nullptr, nullptr, Dv, DFFv);
    ln_k<false><<<Mv, 256>>>(y, out, nullptr, nullptr, gamma2, beta2);
}